// round 1
// baseline (speedup 1.0000x reference)
#include <cuda_runtime.h>

#define Nn 40000
#define Ee 640000
#define ET 680000   /* Ee + Nn self loops */
#define HIDc 128
#define H1c 4
#define D1 512      /* H1*HID */
#define IND 5
#define EDD 11
#define NEG 0.2f

#define EAP_BLOCKS 640
#define EAP_ROWS 1000

#define CAP1 2048
#define CAP2 2048

// ---------------- scratch (device globals; no allocation allowed) ----------
__device__ float g_xh1[(size_t)Nn * D1];
__device__ float g_h1 [(size_t)Nn * D1];
__device__ float g_xh2[(size_t)Nn * HIDc];
__device__ float g_as1[Nn * H1c];
__device__ float g_ad1[Nn * H1c];
__device__ float g_as2[Nn];
__device__ float g_ad2[Nn];
__device__ int   g_deg[Nn];
__device__ int   g_rowstart[Nn + 1];
__device__ int   g_cursor[Nn];
__device__ int   g_csr_src[ET];
__device__ float g_csr_a1[(size_t)ET * H1c];
__device__ float g_csr_e2[ET];
__device__ float g_eamean[EDD];
__device__ float g_eapart[EAP_BLOCKS * EDD];
__device__ float g_aev1[H1c * EDD];
__device__ float g_aev2[EDD];
__device__ float g_us1[H1c * IND];
__device__ float g_ud1[H1c * IND];
__device__ float g_us2[D1];
__device__ float g_ud2[D1];

// ---------------- kernels --------------------------------------------------

__global__ void k_zero_deg() {
    int i = blockIdx.x * blockDim.x + threadIdx.x;
    if (i < Nn) g_deg[i] = 0;
}

// partial column sums of edge_attr, deterministic two-stage reduction
__global__ void k_ea_partial(const float* __restrict__ ea) {
    __shared__ float sm[256 * EDD];
    int b = blockIdx.x, t = threadIdx.x;
    float loc[EDD];
#pragma unroll
    for (int d = 0; d < EDD; d++) loc[d] = 0.f;
    int r0 = b * EAP_ROWS;
    for (int r = t; r < EAP_ROWS; r += 256) {
        const float* p = ea + (size_t)(r0 + r) * EDD;
#pragma unroll
        for (int d = 0; d < EDD; d++) loc[d] += p[d];
    }
#pragma unroll
    for (int d = 0; d < EDD; d++) sm[t * EDD + d] = loc[d];
    __syncthreads();
    for (int off = 128; off > 0; off >>= 1) {
        if (t < off) {
#pragma unroll
            for (int d = 0; d < EDD; d++) sm[t * EDD + d] += sm[(t + off) * EDD + d];
        }
        __syncthreads();
    }
    if (t < EDD) g_eapart[b * EDD + t] = sm[t];
}

// small precompute: ea_mean, ae_vec (edge bilinear vectors), u_src/u_dst
__global__ void k_pre(const float* __restrict__ W1,  const float* __restrict__ We1,
                      const float* __restrict__ as1, const float* __restrict__ ad1,
                      const float* __restrict__ ae1,
                      const float* __restrict__ W2,  const float* __restrict__ We2,
                      const float* __restrict__ as2, const float* __restrict__ ad2,
                      const float* __restrict__ ae2) {
    int t = threadIdx.x;
    if (t < EDD) {
        float s = 0.f;
        for (int b = 0; b < EAP_BLOCKS; b++) s += g_eapart[b * EDD + t];
        g_eamean[t] = s / (float)Ee;
    }
    if (t < H1c * EDD) {            // ae_vec1[h][d] = sum_c We1[d, h*128+c]*a_edge1[h,c]
        int h = t / EDD, d = t % EDD;
        float s = 0.f;
        for (int c = 0; c < HIDc; c++) s += We1[d * D1 + h * HIDc + c] * ae1[h * HIDc + c];
        g_aev1[t] = s;
    }
    if (t < H1c * IND) {            // u_src1/u_dst1[h][d] = sum_c W1[d, h*128+c]*a[h,c]
        int h = t / IND, d = t % IND;
        float s = 0.f, s2 = 0.f;
        for (int c = 0; c < HIDc; c++) {
            float w = W1[d * D1 + h * HIDc + c];
            s  += w * as1[h * HIDc + c];
            s2 += w * ad1[h * HIDc + c];
        }
        g_us1[t] = s; g_ud1[t] = s2;
    }
    if (t < EDD) {                  // ae_vec2[d]
        float s = 0.f;
        for (int c = 0; c < HIDc; c++) s += We2[t * HIDc + c] * ae2[c];
        g_aev2[t] = s;
    }
    for (int k = t; k < D1; k += 256) {  // u_src2/u_dst2[k] = sum_c W2[k,c]*a2[c]
        float s = 0.f, s2 = 0.f;
        for (int c = 0; c < HIDc; c++) {
            float w = W2[k * HIDc + c];
            s  += w * as2[c];
            s2 += w * ad2[c];
        }
        g_us2[k] = s; g_ud2[k] = s2;
    }
}

__global__ void k_count(const int* __restrict__ ei) {
    int e = blockIdx.x * blockDim.x + threadIdx.x;
    if (e >= ET) return;
    int d = (e < Ee) ? ei[Ee + e] : (e - Ee);
    atomicAdd(&g_deg[d], 1);
}

// single-block exclusive scan of deg -> rowstart, cursor
__global__ void k_scan() {
    __shared__ int sm[1024];
    const int CH = (Nn + 1023) / 1024;   // 40
    int t = threadIdx.x;
    int start = t * CH;
    int loc[CH];
    int sum = 0;
#pragma unroll
    for (int i = 0; i < CH; i++) {
        int idx = start + i;
        int v = (idx < Nn) ? g_deg[idx] : 0;
        loc[i] = sum; sum += v;
    }
    sm[t] = sum;
    __syncthreads();
    for (int off = 1; off < 1024; off <<= 1) {
        int v = (t >= off) ? sm[t - off] : 0;
        __syncthreads();
        sm[t] += v;
        __syncthreads();
    }
    int offset = sm[t] - sum;  // exclusive
#pragma unroll
    for (int i = 0; i < CH; i++) {
        int idx = start + i;
        if (idx < Nn) {
            int r = offset + loc[i];
            g_rowstart[idx] = r;
            g_cursor[idx]   = r;
        }
    }
    if (t == 0) g_rowstart[Nn] = ET;
}

// xh1 = x @ W1, plus per-node attention scalars via u-trick
__global__ __launch_bounds__(512) void k_node1(const float* __restrict__ x,
                                               const float* __restrict__ W1) {
    __shared__ float xs[IND];
    int t = threadIdx.x;
    for (int n = blockIdx.x; n < Nn; n += gridDim.x) {
        if (t < IND) xs[t] = x[n * IND + t];
        __syncthreads();
        float v = 0.f;
#pragma unroll
        for (int d = 0; d < IND; d++) v += xs[d] * W1[d * D1 + t];
        g_xh1[(size_t)n * D1 + t] = v;
        if (t < H1c) {
            float s = 0.f;
#pragma unroll
            for (int d = 0; d < IND; d++) s += xs[d] * g_us1[t * IND + d];
            g_as1[n * H1c + t] = s;
        } else if (t < 2 * H1c) {
            int h = t - H1c;
            float s = 0.f;
#pragma unroll
            for (int d = 0; d < IND; d++) s += xs[d] * g_ud1[h * IND + d];
            g_ad1[n * H1c + h] = s;
        }
        __syncthreads();
    }
}

// CSR scatter + per-edge alpha (layer1, post-leakyrelu) and edge-dot (layer2)
__global__ void k_scatter(const int* __restrict__ ei, const float* __restrict__ ea) {
    int e = blockIdx.x * blockDim.x + threadIdx.x;
    if (e >= ET) return;
    int s, d;
    float v[EDD];
    if (e < Ee) {
        s = ei[e]; d = ei[Ee + e];
        const float* p = ea + (size_t)e * EDD;
#pragma unroll
        for (int k = 0; k < EDD; k++) v[k] = p[k];
    } else {
        s = e - Ee; d = s;
#pragma unroll
        for (int k = 0; k < EDD; k++) v[k] = g_eamean[k];
    }
    int pos = atomicAdd(&g_cursor[d], 1);
    g_csr_src[pos] = s;
    float e2 = 0.f;
#pragma unroll
    for (int k = 0; k < EDD; k++) e2 += v[k] * g_aev2[k];
    g_csr_e2[pos] = e2;
#pragma unroll
    for (int h = 0; h < H1c; h++) {
        float ed = 0.f;
#pragma unroll
        for (int k = 0; k < EDD; k++) ed += v[k] * g_aev1[h * EDD + k];
        float al = g_as1[s * H1c + h] + g_ad1[d * H1c + h] + ed;
        g_csr_a1[(size_t)pos * H1c + h] = (al > 0.f) ? al : NEG * al;
    }
}

// layer-1 softmax + aggregation: one block per dst, no atomics, coalesced gather
__global__ __launch_bounds__(512) void k_agg1(const float* __restrict__ b1) {
    int n = blockIdx.x, t = threadIdx.x;
    int h = t >> 7, c = t & 127;
    int base = g_rowstart[n];
    int deg  = g_rowstart[n + 1] - base;
    __shared__ float s_ex[CAP1 * H1c];
    __shared__ int   s_src[CAP1];
    __shared__ float s_part[16];
    __shared__ float s_den[H1c];

    float partial = 0.f;
    for (int i = c; i < deg; i += 128) {
        float ex = __expf(g_csr_a1[(size_t)(base + i) * H1c + h]);
        partial += ex;
        if (i < CAP1) {
            s_ex[i * H1c + h] = ex;
            if (h == 0) s_src[i] = g_csr_src[base + i];
        }
    }
    for (int off = 16; off > 0; off >>= 1)
        partial += __shfl_down_sync(0xffffffffu, partial, off);
    if ((t & 31) == 0) s_part[t >> 5] = partial;
    __syncthreads();
    if (t < H1c)
        s_den[t] = s_part[t * 4] + s_part[t * 4 + 1] + s_part[t * 4 + 2] + s_part[t * 4 + 3];
    __syncthreads();
    float inv = 1.f / (s_den[h] + 1e-16f);

    int staged = deg < CAP1 ? deg : CAP1;
    float acc = 0.f;
    for (int i = 0; i < staged; i++)
        acc += s_ex[i * H1c + h] * g_xh1[(size_t)s_src[i] * D1 + t];
    for (int i = staged; i < deg; i++)   // fallback, effectively never taken
        acc += __expf(g_csr_a1[(size_t)(base + i) * H1c + h]) *
               g_xh1[(size_t)g_csr_src[base + i] * D1 + t];

    float v = acc * inv + b1[t];
    g_h1[(size_t)n * D1 + t] = (v > 0.f) ? v : 0.f;
}

// xh2 = h1 @ W2 : tiled SGEMM, M=40000, N=128, K=512
__global__ __launch_bounds__(256) void k_gemm(const float* __restrict__ B /*W2*/) {
    __shared__ float As[8][128];
    __shared__ float Bs[8][128];
    const float* A = g_h1;
    float*       C = g_xh2;
    int t = threadIdx.x;
    int row0 = blockIdx.x * 128;
    int tr = t >> 4, tc = t & 15;
    float acc[8][8];
#pragma unroll
    for (int i = 0; i < 8; i++)
#pragma unroll
        for (int j = 0; j < 8; j++) acc[i][j] = 0.f;

    int arow = t >> 1, acol = (t & 1) * 4;
    int brow = t >> 5, bcol = (t & 31) * 4;

    for (int k0 = 0; k0 < 512; k0 += 8) {
        int gr = row0 + arow;
        float4 av = make_float4(0.f, 0.f, 0.f, 0.f);
        if (gr < Nn) av = *(const float4*)(A + (size_t)gr * 512 + k0 + acol);
        As[acol + 0][arow] = av.x;
        As[acol + 1][arow] = av.y;
        As[acol + 2][arow] = av.z;
        As[acol + 3][arow] = av.w;
        float4 bv = *(const float4*)(B + (size_t)(k0 + brow) * 128 + bcol);
        *(float4*)(&Bs[brow][bcol]) = bv;
        __syncthreads();
#pragma unroll
        for (int kk = 0; kk < 8; kk++) {
            float ra[8], rb[8];
#pragma unroll
            for (int i = 0; i < 8; i++) ra[i] = As[kk][tr * 8 + i];
#pragma unroll
            for (int j = 0; j < 8; j++) rb[j] = Bs[kk][tc * 8 + j];
#pragma unroll
            for (int i = 0; i < 8; i++)
#pragma unroll
                for (int j = 0; j < 8; j++) acc[i][j] += ra[i] * rb[j];
        }
        __syncthreads();
    }
#pragma unroll
    for (int i = 0; i < 8; i++) {
        int gr = row0 + tr * 8 + i;
        if (gr < Nn) {
            float4 o0 = make_float4(acc[i][0], acc[i][1], acc[i][2], acc[i][3]);
            float4 o1 = make_float4(acc[i][4], acc[i][5], acc[i][6], acc[i][7]);
            *(float4*)(C + (size_t)gr * 128 + tc * 8)     = o0;
            *(float4*)(C + (size_t)gr * 128 + tc * 8 + 4) = o1;
        }
    }
}

// per-node attention scalars for layer 2 (one warp per node)
__global__ void k_attn2() {
    int idx = blockIdx.x * blockDim.x + threadIdx.x;
    int n = idx >> 5;
    if (n >= Nn) return;
    int lane = idx & 31;
    float s = 0.f, d = 0.f;
    for (int i = lane; i < D1; i += 32) {
        float hv = g_h1[(size_t)n * D1 + i];
        s += hv * g_us2[i];
        d += hv * g_ud2[i];
    }
    for (int off = 16; off > 0; off >>= 1) {
        s += __shfl_down_sync(0xffffffffu, s, off);
        d += __shfl_down_sync(0xffffffffu, d, off);
    }
    if (lane == 0) { g_as2[n] = s; g_ad2[n] = d; }
}

// layer-2 softmax + aggregation + final linear + sigmoid, fused per dst
__global__ __launch_bounds__(128) void k_agg2(const float* __restrict__ b2,
                                              const float* __restrict__ Wfc,
                                              const float* __restrict__ bfc,
                                              float* __restrict__ out) {
    int n = blockIdx.x, t = threadIdx.x;
    int base = g_rowstart[n];
    int deg  = g_rowstart[n + 1] - base;
    __shared__ float s_ex[CAP2];
    __shared__ int   s_src[CAP2];
    __shared__ float s_w[4];
    __shared__ float s_den;
    __shared__ float red[128];

    float ad = g_ad2[n];
    float partial = 0.f;
    for (int i = t; i < deg; i += 128) {
        int src = g_csr_src[base + i];
        float al = g_as2[src] + ad + g_csr_e2[base + i];
        al = (al > 0.f) ? al : NEG * al;
        float ex = __expf(al);
        partial += ex;
        if (i < CAP2) { s_ex[i] = ex; s_src[i] = src; }
    }
    for (int off = 16; off > 0; off >>= 1)
        partial += __shfl_down_sync(0xffffffffu, partial, off);
    if ((t & 31) == 0) s_w[t >> 5] = partial;
    __syncthreads();
    if (t == 0) s_den = s_w[0] + s_w[1] + s_w[2] + s_w[3];
    __syncthreads();
    float inv = 1.f / (s_den + 1e-16f);

    int staged = deg < CAP2 ? deg : CAP2;
    float acc = 0.f;
    for (int i = 0; i < staged; i++)
        acc += s_ex[i] * g_xh2[(size_t)s_src[i] * HIDc + t];
    for (int i = staged; i < deg; i++) {
        int src = g_csr_src[base + i];
        float al = g_as2[src] + ad + g_csr_e2[base + i];
        al = (al > 0.f) ? al : NEG * al;
        acc += __expf(al) * g_xh2[(size_t)src * HIDc + t];
    }
    float h2 = acc * inv + b2[t];
    h2 = (h2 > 0.f) ? h2 : 0.f;

    red[t] = h2 * Wfc[t];
    __syncthreads();
    for (int off = 64; off > 0; off >>= 1) {
        if (t < off) red[t] += red[t + off];
        __syncthreads();
    }
    if (t == 0) {
        float z = red[0] + bfc[0];
        out[n] = 1.f / (1.f + __expf(-z));
    }
}

// ---------------- launcher -------------------------------------------------

extern "C" void kernel_launch(void* const* d_in, const int* in_sizes, int n_in,
                              void* d_out, int out_size) {
    const float* x    = (const float*)d_in[0];
    const int*   ei   = (const int*)  d_in[1];
    const float* ea   = (const float*)d_in[2];
    const float* W1   = (const float*)d_in[3];
    const float* We1  = (const float*)d_in[4];
    const float* as1v = (const float*)d_in[5];
    const float* ad1v = (const float*)d_in[6];
    const float* ae1v = (const float*)d_in[7];
    const float* b1   = (const float*)d_in[8];
    const float* W2   = (const float*)d_in[9];
    const float* We2  = (const float*)d_in[10];
    const float* as2v = (const float*)d_in[11];
    const float* ad2v = (const float*)d_in[12];
    const float* ae2v = (const float*)d_in[13];
    const float* b2   = (const float*)d_in[14];
    const float* Wfc  = (const float*)d_in[15];
    const float* bfc  = (const float*)d_in[16];
    float* out = (float*)d_out;

    k_zero_deg<<<(Nn + 255) / 256, 256>>>();
    k_ea_partial<<<EAP_BLOCKS, 256>>>(ea);
    k_pre<<<1, 256>>>(W1, We1, as1v, ad1v, ae1v, W2, We2, as2v, ad2v, ae2v);
    k_count<<<(ET + 255) / 256, 256>>>(ei);
    k_scan<<<1, 1024>>>();
    k_node1<<<2048, 512>>>(x, W1);
    k_scatter<<<(ET + 255) / 256, 256>>>(ei, ea);
    k_agg1<<<Nn, 512>>>(b1);
    k_gemm<<<(Nn + 127) / 128, 256>>>(W2);
    k_attn2<<<(Nn * 32 + 255) / 256, 256>>>();
    k_agg2<<<Nn, 128>>>(b2, Wfc, bfc, out);
}

// round 2
// speedup vs baseline: 1.6233x; 1.6233x over previous
#include <cuda_runtime.h>

#define Nn 40000
#define Ee 640000
#define ET 680000   /* Ee + Nn self loops */
#define HIDc 128
#define H1c 4
#define D1 512      /* H1*HID */
#define IND 5
#define EDD 11
#define NEG 0.2f

#define EAP_BLOCKS 640
#define EAP_ROWS 1000

#define CAP2 96

// ---------------- scratch (device globals; no allocation allowed) ----------
__device__ float g_h1 [(size_t)Nn * D1];
__device__ float g_xh2[(size_t)Nn * HIDc];
__device__ float g_as1[Nn * H1c];
__device__ float g_ad1[Nn * H1c];
__device__ float g_as2[Nn];
__device__ float g_ad2[Nn];
__device__ int   g_deg[Nn];
__device__ int   g_rowstart[Nn + 1];
__device__ int   g_cursor[Nn];
__device__ int   g_csr_src[ET];
__device__ float g_csr_a1[(size_t)ET * H1c];
__device__ float g_csr_e2[ET];
__device__ float g_eamean[EDD];
__device__ float g_eapart[EAP_BLOCKS * EDD];
__device__ float g_aev1[H1c * EDD];
__device__ float g_aev2[EDD];
__device__ float g_us1[H1c * IND];
__device__ float g_ud1[H1c * IND];
__device__ float g_us2[D1];
__device__ float g_ud2[D1];

// ---------------- kernels --------------------------------------------------

__global__ void k_zero_deg() {
    int i = blockIdx.x * blockDim.x + threadIdx.x;
    if (i < Nn) g_deg[i] = 0;
}

// partial column sums of edge_attr, deterministic two-stage reduction
__global__ void k_ea_partial(const float* __restrict__ ea) {
    __shared__ float sm[256 * EDD];
    int b = blockIdx.x, t = threadIdx.x;
    float loc[EDD];
#pragma unroll
    for (int d = 0; d < EDD; d++) loc[d] = 0.f;
    int r0 = b * EAP_ROWS;
    for (int r = t; r < EAP_ROWS; r += 256) {
        const float* p = ea + (size_t)(r0 + r) * EDD;
#pragma unroll
        for (int d = 0; d < EDD; d++) loc[d] += p[d];
    }
#pragma unroll
    for (int d = 0; d < EDD; d++) sm[t * EDD + d] = loc[d];
    __syncthreads();
    for (int off = 128; off > 0; off >>= 1) {
        if (t < off) {
#pragma unroll
            for (int d = 0; d < EDD; d++) sm[t * EDD + d] += sm[(t + off) * EDD + d];
        }
        __syncthreads();
    }
    if (t < EDD) g_eapart[b * EDD + t] = sm[t];
}

// small precompute: ea_mean, ae_vec (edge bilinear vectors), u_src/u_dst
__global__ void k_pre(const float* __restrict__ W1,  const float* __restrict__ We1,
                      const float* __restrict__ as1, const float* __restrict__ ad1,
                      const float* __restrict__ ae1,
                      const float* __restrict__ W2,  const float* __restrict__ We2,
                      const float* __restrict__ as2, const float* __restrict__ ad2,
                      const float* __restrict__ ae2) {
    int t = threadIdx.x;
    if (t < EDD) {
        float s = 0.f;
        for (int b = 0; b < EAP_BLOCKS; b++) s += g_eapart[b * EDD + t];
        g_eamean[t] = s / (float)Ee;
    }
    if (t < H1c * EDD) {            // ae_vec1[h][d] = sum_c We1[d, h*128+c]*a_edge1[h,c]
        int h = t / EDD, d = t % EDD;
        float s = 0.f;
        for (int c = 0; c < HIDc; c++) s += We1[d * D1 + h * HIDc + c] * ae1[h * HIDc + c];
        g_aev1[t] = s;
    }
    if (t < H1c * IND) {            // u_src1/u_dst1[h][d] = sum_c W1[d, h*128+c]*a[h,c]
        int h = t / IND, d = t % IND;
        float s = 0.f, s2 = 0.f;
        for (int c = 0; c < HIDc; c++) {
            float w = W1[d * D1 + h * HIDc + c];
            s  += w * as1[h * HIDc + c];
            s2 += w * ad1[h * HIDc + c];
        }
        g_us1[t] = s; g_ud1[t] = s2;
    }
    if (t < EDD) {                  // ae_vec2[d]
        float s = 0.f;
        for (int c = 0; c < HIDc; c++) s += We2[t * HIDc + c] * ae2[c];
        g_aev2[t] = s;
    }
    for (int k = t; k < D1; k += 256) {  // u_src2/u_dst2[k] = sum_c W2[k,c]*a2[c]
        float s = 0.f, s2 = 0.f;
        for (int c = 0; c < HIDc; c++) {
            float w = W2[k * HIDc + c];
            s  += w * as2[c];
            s2 += w * ad2[c];
        }
        g_us2[k] = s; g_ud2[k] = s2;
    }
}

__global__ void k_count(const int* __restrict__ ei) {
    int e = blockIdx.x * blockDim.x + threadIdx.x;
    if (e >= ET) return;
    int d = (e < Ee) ? ei[Ee + e] : (e - Ee);
    atomicAdd(&g_deg[d], 1);
}

// single-block exclusive scan of deg -> rowstart, cursor
__global__ void k_scan() {
    __shared__ int sm[1024];
    const int CH = (Nn + 1023) / 1024;   // 40
    int t = threadIdx.x;
    int start = t * CH;
    int loc[CH];
    int sum = 0;
#pragma unroll
    for (int i = 0; i < CH; i++) {
        int idx = start + i;
        int v = (idx < Nn) ? g_deg[idx] : 0;
        loc[i] = sum; sum += v;
    }
    sm[t] = sum;
    __syncthreads();
    for (int off = 1; off < 1024; off <<= 1) {
        int v = (t >= off) ? sm[t - off] : 0;
        __syncthreads();
        sm[t] += v;
        __syncthreads();
    }
    int offset = sm[t] - sum;  // exclusive
#pragma unroll
    for (int i = 0; i < CH; i++) {
        int idx = start + i;
        if (idx < Nn) {
            int r = offset + loc[i];
            g_rowstart[idx] = r;
            g_cursor[idx]   = r;
        }
    }
    if (t == 0) g_rowstart[Nn] = ET;
}

// per-node attention scalars for layer 1 (8 threads per node)
__global__ void k_node1(const float* __restrict__ x) {
    int idx = blockIdx.x * blockDim.x + threadIdx.x;
    int n = idx >> 3;
    if (n >= Nn) return;
    int r = idx & 7;
    int h = r & 3;
    const float* xp = x + (size_t)n * IND;
    const float* u = (r < 4) ? (g_us1 + h * IND) : (g_ud1 + h * IND);
    float s = 0.f;
#pragma unroll
    for (int d = 0; d < IND; d++) s += xp[d] * u[d];
    if (r < 4) g_as1[n * H1c + h] = s;
    else       g_ad1[n * H1c + h] = s;
}

// CSR scatter + per-edge alpha (layer1, post-leakyrelu) and edge-dot (layer2)
__global__ void k_scatter(const int* __restrict__ ei, const float* __restrict__ ea) {
    int e = blockIdx.x * blockDim.x + threadIdx.x;
    if (e >= ET) return;
    int s, d;
    float v[EDD];
    if (e < Ee) {
        s = ei[e]; d = ei[Ee + e];
        const float* p = ea + (size_t)e * EDD;
#pragma unroll
        for (int k = 0; k < EDD; k++) v[k] = p[k];
    } else {
        s = e - Ee; d = s;
#pragma unroll
        for (int k = 0; k < EDD; k++) v[k] = g_eamean[k];
    }
    int pos = atomicAdd(&g_cursor[d], 1);
    g_csr_src[pos] = s;
    float e2 = 0.f;
#pragma unroll
    for (int k = 0; k < EDD; k++) e2 += v[k] * g_aev2[k];
    g_csr_e2[pos] = e2;

    float4 asv = *(const float4*)&g_as1[s * H1c];
    float4 adv = *(const float4*)&g_ad1[d * H1c];
    float al[H1c];
#pragma unroll
    for (int h = 0; h < H1c; h++) {
        float ed = 0.f;
#pragma unroll
        for (int k = 0; k < EDD; k++) ed += v[k] * g_aev1[h * EDD + k];
        float a = ((h == 0) ? asv.x : (h == 1) ? asv.y : (h == 2) ? asv.z : asv.w)
                + ((h == 0) ? adv.x : (h == 1) ? adv.y : (h == 2) ? adv.z : adv.w) + ed;
        al[h] = (a > 0.f) ? a : NEG * a;
    }
    *(float4*)&g_csr_a1[(size_t)pos * H1c] = make_float4(al[0], al[1], al[2], al[3]);
}

// layer-1 softmax + aggregation IN INPUT SPACE (5 dims), then project with W1.
// One warp per node, no smem, no atomics.
__global__ __launch_bounds__(256) void k_agg1(const float* __restrict__ x,
                                              const float* __restrict__ W1,
                                              const float* __restrict__ b1) {
    int w = threadIdx.x >> 5;
    int lane = threadIdx.x & 31;
    int n = blockIdx.x * 8 + w;
    if (n >= Nn) return;
    int base = g_rowstart[n];
    int deg  = g_rowstart[n + 1] - base;

    float den[H1c];
    float ax[H1c][IND];
#pragma unroll
    for (int h = 0; h < H1c; h++) {
        den[h] = 0.f;
#pragma unroll
        for (int d = 0; d < IND; d++) ax[h][d] = 0.f;
    }

    for (int i = lane; i < deg; i += 32) {
        int src = g_csr_src[base + i];
        float4 a = *(const float4*)&g_csr_a1[(size_t)(base + i) * H1c];
        float e0 = __expf(a.x), e1 = __expf(a.y), e2 = __expf(a.z), e3 = __expf(a.w);
        den[0] += e0; den[1] += e1; den[2] += e2; den[3] += e3;
        const float* xp = x + (size_t)src * IND;
#pragma unroll
        for (int d = 0; d < IND; d++) {
            float xv = __ldg(xp + d);
            ax[0][d] += e0 * xv;
            ax[1][d] += e1 * xv;
            ax[2][d] += e2 * xv;
            ax[3][d] += e3 * xv;
        }
    }
    // butterfly reduce 24 values across the warp
#pragma unroll
    for (int off = 16; off > 0; off >>= 1) {
#pragma unroll
        for (int h = 0; h < H1c; h++) {
            den[h] += __shfl_xor_sync(0xffffffffu, den[h], off);
#pragma unroll
            for (int d = 0; d < IND; d++)
                ax[h][d] += __shfl_xor_sync(0xffffffffu, ax[h][d], off);
        }
    }
    float inv[H1c];
#pragma unroll
    for (int h = 0; h < H1c; h++) inv[h] = 1.f / (den[h] + 1e-16f);

    // project: h1[n, t] = relu( (ax[h] . W1[:, t]) * inv[h] + b1[t] )
    float* outp = g_h1 + (size_t)n * D1;
#pragma unroll
    for (int j = 0; j < 16; j++) {
        int t = j * 32 + lane;
        int h = t >> 7;
        float acc = 0.f;
#pragma unroll
        for (int d = 0; d < IND; d++) acc = fmaf(ax[h][d], W1[d * D1 + t], acc);
        float v = acc * inv[h] + b1[t];
        outp[t] = (v > 0.f) ? v : 0.f;
    }
}

// xh2 = h1 @ W2 : double-buffered tiled SGEMM, M=40000, N=128, K=512.
// Fused epilogue computes as2/ad2 = h1 . us2 / h1 . ud2 (extra B columns).
__device__ __forceinline__ float4 ldA(int row0, int row, int k) {
    int gr = row0 + row;
    if (gr < Nn) return *(const float4*)(g_h1 + (size_t)gr * D1 + k);
    return make_float4(0.f, 0.f, 0.f, 0.f);
}

__global__ __launch_bounds__(256, 2) void k_gemm(const float* __restrict__ B /*W2*/) {
    __shared__ float As[2][16][128];
    __shared__ float Bs[2][16][128];
    __shared__ float uS[2][16], uD[2][16];
    int t = threadIdx.x;
    int row0 = blockIdx.x * 128;
    int tr = t >> 4, tc = t & 15;

    int row_a = t >> 2, k4_a = (t & 3) * 4;
    int krow_b = t >> 5, col_b = (t & 31) * 4;

    float acc[8][8];
#pragma unroll
    for (int i = 0; i < 8; i++)
#pragma unroll
        for (int j = 0; j < 8; j++) acc[i][j] = 0.f;
    float accS[8], accD[8];
#pragma unroll
    for (int i = 0; i < 8; i++) { accS[i] = 0.f; accD[i] = 0.f; }

    // prefetch tile 0
    float4 pa0 = ldA(row0, row_a, k4_a);
    float4 pa1 = ldA(row0, row_a + 64, k4_a);
    float4 pb0 = *(const float4*)(B + (size_t)krow_b * 128 + col_b);
    float4 pb1 = *(const float4*)(B + (size_t)(8 + krow_b) * 128 + col_b);
    float uSr = 0.f, uDr = 0.f;
    if (t < 16) uSr = g_us2[t];
    else if (t < 32) uDr = g_ud2[t - 16];

    As[0][k4_a + 0][row_a]      = pa0.x;
    As[0][k4_a + 1][row_a]      = pa0.y;
    As[0][k4_a + 2][row_a]      = pa0.z;
    As[0][k4_a + 3][row_a]      = pa0.w;
    As[0][k4_a + 0][row_a + 64] = pa1.x;
    As[0][k4_a + 1][row_a + 64] = pa1.y;
    As[0][k4_a + 2][row_a + 64] = pa1.z;
    As[0][k4_a + 3][row_a + 64] = pa1.w;
    *(float4*)&Bs[0][krow_b][col_b]     = pb0;
    *(float4*)&Bs[0][8 + krow_b][col_b] = pb1;
    if (t < 16) uS[0][t] = uSr;
    else if (t < 32) uD[0][t - 16] = uDr;
    __syncthreads();

    int buf = 0;
    for (int k0 = 0; k0 < 512; k0 += 16) {
        int nk = k0 + 16;
        bool more = (nk < 512);
        if (more) {
            pa0 = ldA(row0, row_a, nk + k4_a);
            pa1 = ldA(row0, row_a + 64, nk + k4_a);
            pb0 = *(const float4*)(B + (size_t)(nk + krow_b) * 128 + col_b);
            pb1 = *(const float4*)(B + (size_t)(nk + 8 + krow_b) * 128 + col_b);
            if (t < 16) uSr = g_us2[nk + t];
            else if (t < 32) uDr = g_ud2[nk + t - 16];
        }
#pragma unroll
        for (int kk = 0; kk < 16; kk++) {
            float4 a0 = *(const float4*)&As[buf][kk][tr * 8];
            float4 a1 = *(const float4*)&As[buf][kk][tr * 8 + 4];
            float4 b0 = *(const float4*)&Bs[buf][kk][tc * 4];
            float4 b1v = *(const float4*)&Bs[buf][kk][64 + tc * 4];
            float ra[8] = {a0.x, a0.y, a0.z, a0.w, a1.x, a1.y, a1.z, a1.w};
            float rb[8] = {b0.x, b0.y, b0.z, b0.w, b1v.x, b1v.y, b1v.z, b1v.w};
#pragma unroll
            for (int i = 0; i < 8; i++)
#pragma unroll
                for (int j = 0; j < 8; j++) acc[i][j] = fmaf(ra[i], rb[j], acc[i][j]);
            if (tc == 0) {
                float us = uS[buf][kk], ud = uD[buf][kk];
#pragma unroll
                for (int i = 0; i < 8; i++) {
                    accS[i] = fmaf(ra[i], us, accS[i]);
                    accD[i] = fmaf(ra[i], ud, accD[i]);
                }
            }
        }
        if (more) {
            int nb = buf ^ 1;
            As[nb][k4_a + 0][row_a]      = pa0.x;
            As[nb][k4_a + 1][row_a]      = pa0.y;
            As[nb][k4_a + 2][row_a]      = pa0.z;
            As[nb][k4_a + 3][row_a]      = pa0.w;
            As[nb][k4_a + 0][row_a + 64] = pa1.x;
            As[nb][k4_a + 1][row_a + 64] = pa1.y;
            As[nb][k4_a + 2][row_a + 64] = pa1.z;
            As[nb][k4_a + 3][row_a + 64] = pa1.w;
            *(float4*)&Bs[nb][krow_b][col_b]     = pb0;
            *(float4*)&Bs[nb][8 + krow_b][col_b] = pb1;
            if (t < 16) uS[nb][t] = uSr;
            else if (t < 32) uD[nb][t - 16] = uDr;
            __syncthreads();
            buf = nb;
        }
    }
#pragma unroll
    for (int i = 0; i < 8; i++) {
        int gr = row0 + tr * 8 + i;
        if (gr < Nn) {
            *(float4*)(g_xh2 + (size_t)gr * 128 + tc * 4) =
                make_float4(acc[i][0], acc[i][1], acc[i][2], acc[i][3]);
            *(float4*)(g_xh2 + (size_t)gr * 128 + 64 + tc * 4) =
                make_float4(acc[i][4], acc[i][5], acc[i][6], acc[i][7]);
            if (tc == 0) { g_as2[gr] = accS[i]; g_ad2[gr] = accD[i]; }
        }
    }
}

// layer-2 softmax + aggregation + final linear + sigmoid, fused per dst
__global__ __launch_bounds__(128) void k_agg2(const float* __restrict__ b2,
                                              const float* __restrict__ Wfc,
                                              const float* __restrict__ bfc,
                                              float* __restrict__ out) {
    int n = blockIdx.x, t = threadIdx.x;
    int base = g_rowstart[n];
    int deg  = g_rowstart[n + 1] - base;
    __shared__ float s_ex[CAP2];
    __shared__ int   s_src[CAP2];
    __shared__ float s_w[4];
    __shared__ float s_den;
    __shared__ float red[128];

    float ad = g_ad2[n];
    float partial = 0.f;
    for (int i = t; i < deg; i += 128) {
        int src = g_csr_src[base + i];
        float al = g_as2[src] + ad + g_csr_e2[base + i];
        al = (al > 0.f) ? al : NEG * al;
        float ex = __expf(al);
        partial += ex;
        if (i < CAP2) { s_ex[i] = ex; s_src[i] = src; }
    }
    for (int off = 16; off > 0; off >>= 1)
        partial += __shfl_down_sync(0xffffffffu, partial, off);
    if ((t & 31) == 0) s_w[t >> 5] = partial;
    __syncthreads();
    if (t == 0) s_den = s_w[0] + s_w[1] + s_w[2] + s_w[3];
    __syncthreads();
    float inv = 1.f / (s_den + 1e-16f);

    int staged = deg < CAP2 ? deg : CAP2;
    float a0 = 0.f, a1 = 0.f, a2 = 0.f, a3 = 0.f;
    int i = 0;
    for (; i + 4 <= staged; i += 4) {
        a0 = fmaf(s_ex[i + 0], g_xh2[(size_t)s_src[i + 0] * HIDc + t], a0);
        a1 = fmaf(s_ex[i + 1], g_xh2[(size_t)s_src[i + 1] * HIDc + t], a1);
        a2 = fmaf(s_ex[i + 2], g_xh2[(size_t)s_src[i + 2] * HIDc + t], a2);
        a3 = fmaf(s_ex[i + 3], g_xh2[(size_t)s_src[i + 3] * HIDc + t], a3);
    }
    for (; i < staged; i++)
        a0 = fmaf(s_ex[i], g_xh2[(size_t)s_src[i] * HIDc + t], a0);
    float acc = (a0 + a1) + (a2 + a3);
    for (i = staged; i < deg; i++) {   // fallback, effectively never taken
        int src = g_csr_src[base + i];
        float al = g_as2[src] + ad + g_csr_e2[base + i];
        al = (al > 0.f) ? al : NEG * al;
        acc = fmaf(__expf(al), g_xh2[(size_t)src * HIDc + t], acc);
    }
    float h2 = acc * inv + b2[t];
    h2 = (h2 > 0.f) ? h2 : 0.f;

    red[t] = h2 * Wfc[t];
    __syncthreads();
    for (int off = 64; off > 0; off >>= 1) {
        if (t < off) red[t] += red[t + off];
        __syncthreads();
    }
    if (t == 0) {
        float z = red[0] + bfc[0];
        out[n] = 1.f / (1.f + __expf(-z));
    }
}

// ---------------- launcher -------------------------------------------------

extern "C" void kernel_launch(void* const* d_in, const int* in_sizes, int n_in,
                              void* d_out, int out_size) {
    const float* x    = (const float*)d_in[0];
    const int*   ei   = (const int*)  d_in[1];
    const float* ea   = (const float*)d_in[2];
    const float* W1   = (const float*)d_in[3];
    const float* We1  = (const float*)d_in[4];
    const float* as1v = (const float*)d_in[5];
    const float* ad1v = (const float*)d_in[6];
    const float* ae1v = (const float*)d_in[7];
    const float* b1   = (const float*)d_in[8];
    const float* W2   = (const float*)d_in[9];
    const float* We2  = (const float*)d_in[10];
    const float* as2v = (const float*)d_in[11];
    const float* ad2v = (const float*)d_in[12];
    const float* ae2v = (const float*)d_in[13];
    const float* b2   = (const float*)d_in[14];
    const float* Wfc  = (const float*)d_in[15];
    const float* bfc  = (const float*)d_in[16];
    float* out = (float*)d_out;

    k_zero_deg<<<(Nn + 255) / 256, 256>>>();
    k_ea_partial<<<EAP_BLOCKS, 256>>>(ea);
    k_pre<<<1, 256>>>(W1, We1, as1v, ad1v, ae1v, W2, We2, as2v, ad2v, ae2v);
    k_count<<<(ET + 255) / 256, 256>>>(ei);
    k_scan<<<1, 1024>>>();
    k_node1<<<(Nn * 8 + 255) / 256, 256>>>(x);
    k_scatter<<<(ET + 255) / 256, 256>>>(ei, ea);
    k_agg1<<<(Nn + 7) / 8, 256>>>(x, W1, b1);
    k_gemm<<<(Nn + 127) / 128, 256>>>(W2);
    k_agg2<<<Nn, 128>>>(b2, Wfc, bfc, out);
}

// round 5
// speedup vs baseline: 2.6225x; 1.6155x over previous
#include <cuda_runtime.h>
#include <cuda_bf16.h>
#include <mma.h>
#include <cstdint>

using namespace nvcuda;

#define Nn 40000
#define Ee 640000
#define ET 680000   /* Ee + Nn self loops */
#define HIDc 128
#define H1c 4
#define D1 512      /* H1*HID */
#define IND 5
#define EDD 11
#define NEG 0.2f

#define EAP_BLOCKS 640
#define EAP_ROWS 1000
#define CAP2 96

#define MROWS 40064          /* 313 * 128, padded M */

// ---------------- scratch (device globals; no allocation allowed) ----------
__device__ __nv_bfloat16 g_h1b[(size_t)MROWS * D1];     // padded rows stay zero
__device__ float g_xh2[(size_t)MROWS * HIDc];           // padded rows writable
__device__ __nv_bfloat16 g_W2b[D1 * HIDc];
__device__ float g_as1[Nn * H1c];
__device__ float g_ad1[Nn * H1c];
__device__ float g_as2[Nn];
__device__ float g_ad2[Nn];
__device__ int   g_deg[Nn];
__device__ int   g_rowstart[Nn + 1];
__device__ int   g_cursor[Nn];
__device__ int   g_csr_src[ET];
__device__ float g_csr_a1[(size_t)ET * H1c];
__device__ float g_csr_e2[ET];
__device__ float g_eamean[EDD];
__device__ float g_eapart[EAP_BLOCKS * EDD];
__device__ float g_aev1[H1c * EDD];
__device__ float g_aev2[EDD];
__device__ float g_us1[H1c * IND];
__device__ float g_ud1[H1c * IND];
__device__ float g_us2[D1];
__device__ float g_ud2[D1];

// ---------------- small helpers --------------------------------------------
__device__ __forceinline__ uint32_t smem_u32(const void* p) {
    uint32_t a;
    asm("{ .reg .u64 t; cvta.to.shared.u64 t, %1; cvt.u32.u64 %0, t; }" : "=r"(a) : "l"(p));
    return a;
}
__device__ __forceinline__ void cp_async16(uint32_t dst, const void* src) {
    asm volatile("cp.async.cg.shared.global [%0], [%1], 16;" :: "r"(dst), "l"(src));
}
#define CP_COMMIT() asm volatile("cp.async.commit_group;" ::: "memory")
#define CP_WAIT1()  asm volatile("cp.async.wait_group 1;" ::: "memory")
#define CP_WAIT0()  asm volatile("cp.async.wait_group 0;" ::: "memory")

// ---------------- kernels --------------------------------------------------

__global__ void k_zero_deg() {
    int i = blockIdx.x * blockDim.x + threadIdx.x;
    if (i < Nn) g_deg[i] = 0;
}

__global__ void k_ea_partial(const float* __restrict__ ea) {
    __shared__ float sm[256 * EDD];
    int b = blockIdx.x, t = threadIdx.x;
    float loc[EDD];
#pragma unroll
    for (int d = 0; d < EDD; d++) loc[d] = 0.f;
    int r0 = b * EAP_ROWS;
    for (int r = t; r < EAP_ROWS; r += 256) {
        const float* p = ea + (size_t)(r0 + r) * EDD;
#pragma unroll
        for (int d = 0; d < EDD; d++) loc[d] += p[d];
    }
#pragma unroll
    for (int d = 0; d < EDD; d++) sm[t * EDD + d] = loc[d];
    __syncthreads();
    for (int off = 128; off > 0; off >>= 1) {
        if (t < off) {
#pragma unroll
            for (int d = 0; d < EDD; d++) sm[t * EDD + d] += sm[(t + off) * EDD + d];
        }
        __syncthreads();
    }
    if (t < EDD) g_eapart[b * EDD + t] = sm[t];
}

__global__ void k_pre(const float* __restrict__ W1,  const float* __restrict__ We1,
                      const float* __restrict__ as1, const float* __restrict__ ad1,
                      const float* __restrict__ ae1,
                      const float* __restrict__ W2,  const float* __restrict__ We2,
                      const float* __restrict__ as2, const float* __restrict__ ad2,
                      const float* __restrict__ ae2) {
    int t = threadIdx.x;
    if (t < EDD) {
        float s = 0.f;
        for (int b = 0; b < EAP_BLOCKS; b++) s += g_eapart[b * EDD + t];
        g_eamean[t] = s / (float)Ee;
    }
    if (t < H1c * EDD) {
        int h = t / EDD, d = t % EDD;
        float s = 0.f;
        for (int c = 0; c < HIDc; c++) s += We1[d * D1 + h * HIDc + c] * ae1[h * HIDc + c];
        g_aev1[t] = s;
    }
    if (t < H1c * IND) {
        int h = t / IND, d = t % IND;
        float s = 0.f, s2 = 0.f;
        for (int c = 0; c < HIDc; c++) {
            float w = W1[d * D1 + h * HIDc + c];
            s  += w * as1[h * HIDc + c];
            s2 += w * ad1[h * HIDc + c];
        }
        g_us1[t] = s; g_ud1[t] = s2;
    }
    if (t < EDD) {
        float s = 0.f;
        for (int c = 0; c < HIDc; c++) s += We2[t * HIDc + c] * ae2[c];
        g_aev2[t] = s;
    }
    for (int k = t; k < D1; k += 256) {
        float s = 0.f, s2 = 0.f;
        for (int c = 0; c < HIDc; c++) {
            float w = W2[k * HIDc + c];
            s  += w * as2[c];
            s2 += w * ad2[c];
        }
        g_us2[k] = s; g_ud2[k] = s2;
    }
}

// W2 fp32 -> bf16 linear
__global__ void k_prepB(const float* __restrict__ W2) {
    int idx = blockIdx.x * blockDim.x + threadIdx.x;   // 65536
    g_W2b[idx] = __float2bfloat16(W2[idx]);
}

__global__ void k_count(const int* __restrict__ ei) {
    int e = blockIdx.x * blockDim.x + threadIdx.x;
    if (e >= ET) return;
    int d = (e < Ee) ? ei[Ee + e] : (e - Ee);
    atomicAdd(&g_deg[d], 1);
}

__global__ void k_scan() {
    __shared__ int sm[1024];
    const int CH = (Nn + 1023) / 1024;   // 40
    int t = threadIdx.x;
    int start = t * CH;
    int loc[CH];
    int sum = 0;
#pragma unroll
    for (int i = 0; i < CH; i++) {
        int idx = start + i;
        int v = (idx < Nn) ? g_deg[idx] : 0;
        loc[i] = sum; sum += v;
    }
    sm[t] = sum;
    __syncthreads();
    for (int off = 1; off < 1024; off <<= 1) {
        int v = (t >= off) ? sm[t - off] : 0;
        __syncthreads();
        sm[t] += v;
        __syncthreads();
    }
    int offset = sm[t] - sum;
#pragma unroll
    for (int i = 0; i < CH; i++) {
        int idx = start + i;
        if (idx < Nn) {
            int r = offset + loc[i];
            g_rowstart[idx] = r;
            g_cursor[idx]   = r;
        }
    }
    if (t == 0) g_rowstart[Nn] = ET;
}

__global__ void k_node1(const float* __restrict__ x) {
    int idx = blockIdx.x * blockDim.x + threadIdx.x;
    int n = idx >> 3;
    if (n >= Nn) return;
    int r = idx & 7;
    int h = r & 3;
    const float* xp = x + (size_t)n * IND;
    const float* u = (r < 4) ? (g_us1 + h * IND) : (g_ud1 + h * IND);
    float s = 0.f;
#pragma unroll
    for (int d = 0; d < IND; d++) s += xp[d] * u[d];
    if (r < 4) g_as1[n * H1c + h] = s;
    else       g_ad1[n * H1c + h] = s;
}

__global__ void k_scatter(const int* __restrict__ ei, const float* __restrict__ ea) {
    int e = blockIdx.x * blockDim.x + threadIdx.x;
    if (e >= ET) return;
    int s, d;
    float v[EDD];
    if (e < Ee) {
        s = ei[e]; d = ei[Ee + e];
        const float* p = ea + (size_t)e * EDD;
#pragma unroll
        for (int k = 0; k < EDD; k++) v[k] = p[k];
    } else {
        s = e - Ee; d = s;
#pragma unroll
        for (int k = 0; k < EDD; k++) v[k] = g_eamean[k];
    }
    int pos = atomicAdd(&g_cursor[d], 1);
    g_csr_src[pos] = s;
    float e2 = 0.f;
#pragma unroll
    for (int k = 0; k < EDD; k++) e2 += v[k] * g_aev2[k];
    g_csr_e2[pos] = e2;

    float4 asv = *(const float4*)&g_as1[s * H1c];
    float4 adv = *(const float4*)&g_ad1[d * H1c];
    float al[H1c];
#pragma unroll
    for (int h = 0; h < H1c; h++) {
        float ed = 0.f;
#pragma unroll
        for (int k = 0; k < EDD; k++) ed += v[k] * g_aev1[h * EDD + k];
        float a = ((h == 0) ? asv.x : (h == 1) ? asv.y : (h == 2) ? asv.z : asv.w)
                + ((h == 0) ? adv.x : (h == 1) ? adv.y : (h == 2) ? adv.z : adv.w) + ed;
        al[h] = (a > 0.f) ? a : NEG * a;
    }
    *(float4*)&g_csr_a1[(size_t)pos * H1c] = make_float4(al[0], al[1], al[2], al[3]);
}

// layer-1 softmax + aggregation in input space, project with W1, emit bf16 h1,
// and fuse the layer-2 attention logits (fp32, pre-rounding). One warp per node.
__global__ __launch_bounds__(256) void k_agg1(const float* __restrict__ x,
                                              const float* __restrict__ W1,
                                              const float* __restrict__ b1) {
    int w = threadIdx.x >> 5;
    int lane = threadIdx.x & 31;
    int n = blockIdx.x * 8 + w;
    if (n >= Nn) return;
    int base = g_rowstart[n];
    int deg  = g_rowstart[n + 1] - base;

    float den[H1c];
    float ax[H1c][IND];
#pragma unroll
    for (int h = 0; h < H1c; h++) {
        den[h] = 0.f;
#pragma unroll
        for (int d = 0; d < IND; d++) ax[h][d] = 0.f;
    }

    for (int i = lane; i < deg; i += 32) {
        int src = g_csr_src[base + i];
        float4 a = *(const float4*)&g_csr_a1[(size_t)(base + i) * H1c];
        float e0 = __expf(a.x), e1 = __expf(a.y), e2 = __expf(a.z), e3 = __expf(a.w);
        den[0] += e0; den[1] += e1; den[2] += e2; den[3] += e3;
        const float* xp = x + (size_t)src * IND;
#pragma unroll
        for (int d = 0; d < IND; d++) {
            float xv = __ldg(xp + d);
            ax[0][d] += e0 * xv;
            ax[1][d] += e1 * xv;
            ax[2][d] += e2 * xv;
            ax[3][d] += e3 * xv;
        }
    }
#pragma unroll
    for (int off = 16; off > 0; off >>= 1) {
#pragma unroll
        for (int h = 0; h < H1c; h++) {
            den[h] += __shfl_xor_sync(0xffffffffu, den[h], off);
#pragma unroll
            for (int d = 0; d < IND; d++)
                ax[h][d] += __shfl_xor_sync(0xffffffffu, ax[h][d], off);
        }
    }
    float inv[H1c];
#pragma unroll
    for (int h = 0; h < H1c; h++) inv[h] = 1.f / (den[h] + 1e-16f);

    __nv_bfloat16* outp = g_h1b + (size_t)n * D1;
    float s2 = 0.f, d2v = 0.f;
#pragma unroll
    for (int j = 0; j < 16; j++) {
        int t = j * 32 + lane;
        int h = t >> 7;
        float acc = 0.f;
#pragma unroll
        for (int d = 0; d < IND; d++) acc = fmaf(ax[h][d], W1[d * D1 + t], acc);
        float v = acc * inv[h] + b1[t];
        v = (v > 0.f) ? v : 0.f;
        outp[t] = __float2bfloat16(v);
        s2  = fmaf(v, g_us2[t], s2);
        d2v = fmaf(v, g_ud2[t], d2v);
    }
#pragma unroll
    for (int off = 16; off > 0; off >>= 1) {
        s2  += __shfl_xor_sync(0xffffffffu, s2, off);
        d2v += __shfl_xor_sync(0xffffffffu, d2v, off);
    }
    if (lane == 0) { g_as2[n] = s2; g_ad2[n] = d2v; }
}

// xh2 = h1 @ W2 : bf16 wmma (HMMA), 128x128 CTA tile, K chunks of 64,
// cp.async double-buffered.  A [128][72] padded, B [64][136] padded.
#define KC 64
#define A_ELEMS 9216    /* 128 * 72 */
#define B_ELEMS 8704    /* 64 * 136 */
#define A_BYTES 18432
#define B_BYTES 17408
#define GSM_TOTAL (2 * (A_BYTES + B_BYTES))   /* 71680 */

__global__ __launch_bounds__(256, 2) void k_gemm() {
    extern __shared__ char smc[];
    __nv_bfloat16* As = (__nv_bfloat16*)smc;                     // [2][128][72]
    __nv_bfloat16* Bs = (__nv_bfloat16*)(smc + 2 * A_BYTES);     // [2][64][136]
    uint32_t smA = smem_u32(As);
    uint32_t smB = smem_u32(Bs);

    int t = threadIdx.x;
    int wid = t >> 5;
    int row0 = blockIdx.x * 128;
    int wm0 = (wid >> 2) * 64;     // 0 or 64
    int wn0 = (wid & 3) * 32;      // 0,32,64,96

    wmma::fragment<wmma::accumulator, 16, 16, 16, float> acc[4][2];
#pragma unroll
    for (int m = 0; m < 4; m++)
#pragma unroll
        for (int n = 0; n < 2; n++) wmma::fill_fragment(acc[m][n], 0.f);

    auto load_chunk = [&](int buf, int k0) {
#pragma unroll
        for (int i = 0; i < 4; i++) {
            int v = i * 256 + t;
            int r = v >> 3, c8 = v & 7;                 // A: 128 rows x 8 uint4
            cp_async16(smA + (uint32_t)(buf * A_ELEMS + r * 72 + c8 * 8) * 2,
                       g_h1b + (size_t)(row0 + r) * D1 + k0 + c8 * 8);
        }
#pragma unroll
        for (int i = 0; i < 4; i++) {
            int v = i * 256 + t;
            int r = v >> 4, c8 = v & 15;                // B: 64 rows x 16 uint4
            cp_async16(smB + (uint32_t)(buf * B_ELEMS + r * 136 + c8 * 8) * 2,
                       g_W2b + (size_t)(k0 + r) * HIDc + c8 * 8);
        }
        CP_COMMIT();
    };

    load_chunk(0, 0);
    int buf = 0;
#pragma unroll
    for (int c = 0; c < 8; c++) {
        if (c < 7) load_chunk(buf ^ 1, (c + 1) * KC);
        if (c < 7) CP_WAIT1(); else CP_WAIT0();
        __syncthreads();

        const __nv_bfloat16* Ab = As + buf * A_ELEMS;
        const __nv_bfloat16* Bb = Bs + buf * B_ELEMS;
#pragma unroll
        for (int kk = 0; kk < 4; kk++) {
            wmma::fragment<wmma::matrix_a, 16, 16, 16, __nv_bfloat16, wmma::row_major> af[4];
            wmma::fragment<wmma::matrix_b, 16, 16, 16, __nv_bfloat16, wmma::row_major> bf[2];
#pragma unroll
            for (int m = 0; m < 4; m++)
                wmma::load_matrix_sync(af[m], Ab + (wm0 + m * 16) * 72 + kk * 16, 72);
#pragma unroll
            for (int n = 0; n < 2; n++)
                wmma::load_matrix_sync(bf[n], Bb + (kk * 16) * 136 + wn0 + n * 16, 136);
#pragma unroll
            for (int m = 0; m < 4; m++)
#pragma unroll
                for (int n = 0; n < 2; n++)
                    wmma::mma_sync(acc[m][n], af[m], bf[n], acc[m][n]);
        }
        __syncthreads();
        buf ^= 1;
    }

#pragma unroll
    for (int m = 0; m < 4; m++)
#pragma unroll
        for (int n = 0; n < 2; n++)
            wmma::store_matrix_sync(
                g_xh2 + (size_t)(row0 + wm0 + m * 16) * HIDc + wn0 + n * 16,
                acc[m][n], HIDc, wmma::mem_row_major);
}

// layer-2 softmax + aggregation + final linear + sigmoid, fused per dst
__global__ __launch_bounds__(128) void k_agg2(const float* __restrict__ b2,
                                              const float* __restrict__ Wfc,
                                              const float* __restrict__ bfc,
                                              float* __restrict__ out) {
    int n = blockIdx.x, t = threadIdx.x;
    int base = g_rowstart[n];
    int deg  = g_rowstart[n + 1] - base;
    __shared__ float s_ex[CAP2];
    __shared__ int   s_src[CAP2];
    __shared__ float s_w[4];
    __shared__ float s_den;
    __shared__ float red[128];

    float ad = g_ad2[n];
    float partial = 0.f;
    for (int i = t; i < deg; i += 128) {
        int src = g_csr_src[base + i];
        float al = g_as2[src] + ad + g_csr_e2[base + i];
        al = (al > 0.f) ? al : NEG * al;
        float ex = __expf(al);
        partial += ex;
        if (i < CAP2) { s_ex[i] = ex; s_src[i] = src; }
    }
    for (int off = 16; off > 0; off >>= 1)
        partial += __shfl_down_sync(0xffffffffu, partial, off);
    if ((t & 31) == 0) s_w[t >> 5] = partial;
    __syncthreads();
    if (t == 0) s_den = s_w[0] + s_w[1] + s_w[2] + s_w[3];
    __syncthreads();
    float inv = 1.f / (s_den + 1e-16f);

    int staged = deg < CAP2 ? deg : CAP2;
    float a0 = 0.f, a1 = 0.f, a2 = 0.f, a3 = 0.f;
    int i = 0;
    for (; i + 4 <= staged; i += 4) {
        a0 = fmaf(s_ex[i + 0], g_xh2[(size_t)s_src[i + 0] * HIDc + t], a0);
        a1 = fmaf(s_ex[i + 1], g_xh2[(size_t)s_src[i + 1] * HIDc + t], a1);
        a2 = fmaf(s_ex[i + 2], g_xh2[(size_t)s_src[i + 2] * HIDc + t], a2);
        a3 = fmaf(s_ex[i + 3], g_xh2[(size_t)s_src[i + 3] * HIDc + t], a3);
    }
    for (; i < staged; i++)
        a0 = fmaf(s_ex[i], g_xh2[(size_t)s_src[i] * HIDc + t], a0);
    float acc = (a0 + a1) + (a2 + a3);
    for (i = staged; i < deg; i++) {
        int src = g_csr_src[base + i];
        float al = g_as2[src] + ad + g_csr_e2[base + i];
        al = (al > 0.f) ? al : NEG * al;
        acc = fmaf(__expf(al), g_xh2[(size_t)src * HIDc + t], acc);
    }
    float h2 = acc * inv + b2[t];
    h2 = (h2 > 0.f) ? h2 : 0.f;

    red[t] = h2 * Wfc[t];
    __syncthreads();
    for (int off = 64; off > 0; off >>= 1) {
        if (t < off) red[t] += red[t + off];
        __syncthreads();
    }
    if (t == 0) {
        float z = red[0] + bfc[0];
        out[n] = 1.f / (1.f + __expf(-z));
    }
}

// ---------------- launcher -------------------------------------------------

extern "C" void kernel_launch(void* const* d_in, const int* in_sizes, int n_in,
                              void* d_out, int out_size) {
    const float* x    = (const float*)d_in[0];
    const int*   ei   = (const int*)  d_in[1];
    const float* ea   = (const float*)d_in[2];
    const float* W1   = (const float*)d_in[3];
    const float* We1  = (const float*)d_in[4];
    const float* as1v = (const float*)d_in[5];
    const float* ad1v = (const float*)d_in[6];
    const float* ae1v = (const float*)d_in[7];
    const float* b1   = (const float*)d_in[8];
    const float* W2   = (const float*)d_in[9];
    const float* We2  = (const float*)d_in[10];
    const float* as2v = (const float*)d_in[11];
    const float* ad2v = (const float*)d_in[12];
    const float* ae2v = (const float*)d_in[13];
    const float* b2   = (const float*)d_in[14];
    const float* Wfc  = (const float*)d_in[15];
    const float* bfc  = (const float*)d_in[16];
    float* out = (float*)d_out;

    static int attr_set = 0;
    if (!attr_set) {
        cudaFuncSetAttribute(k_gemm, cudaFuncAttributeMaxDynamicSharedMemorySize, GSM_TOTAL);
        attr_set = 1;
    }

    k_zero_deg<<<(Nn + 255) / 256, 256>>>();
    k_ea_partial<<<EAP_BLOCKS, 256>>>(ea);
    k_pre<<<1, 256>>>(W1, We1, as1v, ad1v, ae1v, W2, We2, as2v, ad2v, ae2v);
    k_prepB<<<256, 256>>>(W2);
    k_count<<<(ET + 255) / 256, 256>>>(ei);
    k_scan<<<1, 1024>>>();
    k_node1<<<(Nn * 8 + 255) / 256, 256>>>(x);
    k_scatter<<<(ET + 255) / 256, 256>>>(ei, ea);
    k_agg1<<<(Nn + 7) / 8, 256>>>(x, W1, b1);
    k_gemm<<<MROWS / 128, 256, GSM_TOTAL>>>();
    k_agg2<<<Nn, 128>>>(b2, Wfc, bfc, out);
}